// round 3
// baseline (speedup 1.0000x reference)
#include <cuda_runtime.h>
#include <math_constants.h>

// SparsemaxBisect: 4096 rows x 32000 fp32, alpha=2.
// Closed-form sparsemax threshold over the ~20-40 candidates > rowmax-1
// (reference's 50 bisections converge to this exactly).
// Key scheduling idea: tau >= warp_max-1, so each warp writes exact zeros for
// its sub-threshold elements immediately after loading (no block barrier),
// overlapping 99.9% of store traffic with the reduce/collect/solve.
// Persistent CTAs with atomic row-stealing remove wave-transition overhead.

#define D_LEN       32000
#define V4_PER_ROW  8000
#define THREADS     1024
#define NWARP       32
#define PER_THREAD  8
#define CAND_CAP    1024
#define SORT_CAP    256
#define NEG_INF     (-CUDART_INF_F)

__device__ unsigned int g_row_ctr;

__global__ void reset_ctr_kernel() { g_row_ctr = 0u; }

__global__ __launch_bounds__(THREADS, 1)
void sparsemax_kernel(const float* __restrict__ X,
                      float* __restrict__ Out,
                      int nrows)
{
    const int t    = threadIdx.x;
    const int lane = t & 31;
    const int w    = t >> 5;

    __shared__ float s_warpred[NWARP];
    __shared__ int   s_row;
    __shared__ int   s_cnt;
    __shared__ float s_cand[CAND_CAP];
    __shared__ float s_sorted[NWARP][SORT_CAP];   // per-warp redundant solve

    while (true) {
        // ---- fetch next row (dynamic stealing), reset candidate count ----
        if (t == 0) {
            s_row = (int)atomicAdd(&g_row_ctr, 1u);
            s_cnt = 0;
        }
        __syncthreads();                               // B0
        const int row = s_row;
        if (row >= nrows) break;

        const float4* __restrict__ xr =
            reinterpret_cast<const float4*>(X + (size_t)row * D_LEN);
        float4* __restrict__ orow =
            reinterpret_cast<float4*>(Out + (size_t)row * D_LEN);

        // ---- load row into registers (front-batched LDG.128, streaming) ----
        float4 v[PER_THREAD];
#pragma unroll
        for (int j = 0; j < PER_THREAD; j++) {
            int idx = t + j * THREADS;
            v[j] = (idx < V4_PER_ROW) ? __ldcs(&xr[idx])
                 : make_float4(NEG_INF, NEG_INF, NEG_INF, NEG_INF);
        }

        // ---- warp max (no block barrier needed yet) ----
        float wm = NEG_INF;
#pragma unroll
        for (int j = 0; j < PER_THREAD; j++)
            wm = fmaxf(wm, fmaxf(fmaxf(v[j].x, v[j].y), fmaxf(v[j].z, v[j].w)));
#pragma unroll
        for (int o = 16; o > 0; o >>= 1)
            wm = fmaxf(wm, __shfl_xor_sync(0xFFFFFFFFu, wm, o));
        if (lane == 0) s_warpred[w] = wm;
        const float wthr = wm - 1.0f;

        // ---- EARLY zero-writes: x <= warp_max-1 <= tau  =>  output exactly 0 ----
        unsigned dmask = 0;
        const float4 z4 = make_float4(0.f, 0.f, 0.f, 0.f);
#pragma unroll
        for (int j = 0; j < PER_THREAD; j++) {
            int idx = t + j * THREADS;
            if (idx < V4_PER_ROW) {
                float m4 = fmaxf(fmaxf(v[j].x, v[j].y), fmaxf(v[j].z, v[j].w));
                if (m4 > wthr) dmask |= (1u << j);     // defer this float4
                else           __stcs(&orow[idx], z4); // final value, write now
            }
        }
        __syncthreads();                               // B1: s_warpred complete

        // ---- global max (each warp reduces the 32 warp maxima redundantly) ----
        float gm = s_warpred[lane];
#pragma unroll
        for (int o = 16; o > 0; o >>= 1)
            gm = fmaxf(gm, __shfl_xor_sync(0xFFFFFFFFu, gm, o));
        const float gthr = gm - 1.0f;

        // ---- candidate collection (only deferred float4s can hold candidates) ----
        if (__ballot_sync(0xFFFFFFFFu, dmask != 0u)) {
#pragma unroll
            for (int j = 0; j < PER_THREAD; j++) {
                unsigned bj = __ballot_sync(0xFFFFFFFFu, (dmask >> j) & 1u);
                if (!bj) continue;
                float c[4] = {v[j].x, v[j].y, v[j].z, v[j].w};
                bool def = (dmask >> j) & 1u;
#pragma unroll
                for (int e = 0; e < 4; e++) {
                    bool pred = def && (c[e] > gthr);
                    unsigned m = __ballot_sync(0xFFFFFFFFu, pred);
                    if (m) {
                        int leader = __ffs(m) - 1;
                        int base = 0;
                        if (lane == leader) base = atomicAdd(&s_cnt, __popc(m));
                        base = __shfl_sync(0xFFFFFFFFu, base, leader);
                        if (pred) {
                            int p = base + __popc(m & ((1u << lane) - 1u));
                            if (p < CAND_CAP) s_cand[p] = c[e];
                        }
                    }
                }
            }
        }
        __syncthreads();                               // B2: s_cand complete

        // ---- every warp redundantly solves tau in closed form ----
        int cnt = s_cnt;
        cnt = (cnt < SORT_CAP) ? cnt : SORT_CAP;

        float* srt = s_sorted[w];
        for (int i = lane; i < cnt; i += 32) {
            float ci = s_cand[i];
            int r = 0;
            for (int jj = 0; jj < cnt; jj++) {
                float cj = s_cand[jj];
                r += (cj > ci) || (cj == ci && jj < i);
            }
            srt[r] = ci;
        }
        __syncwarp();

        // support rule: k* = max{ j : c_(j) * j > S_j - 1 },  tau = (S_k* - 1)/k*
        float Srun = 0.0f;
        int   kbest = 1;
        float Sbest = 0.0f;
        for (int base = 0; base < cnt; base += 32) {
            int idx = base + lane;
            float c = (idx < cnt) ? srt[idx] : 0.0f;
            float x = c;
#pragma unroll
            for (int o = 1; o < 32; o <<= 1) {
                float y = __shfl_up_sync(0xFFFFFFFFu, x, o);
                if (lane >= o) x += y;
            }
            float Sj = Srun + x;
            bool cond = (idx < cnt) && (c * (float)(idx + 1) > Sj - 1.0f);
            unsigned b = __ballot_sync(0xFFFFFFFFu, cond);
            if (b) {
                int hi = 31 - __clz(b);
                Sbest = __shfl_sync(0xFFFFFFFFu, Sj, hi);
                kbest = base + hi + 1;
            }
            Srun += __shfl_sync(0xFFFFFFFFu, x, 31);
        }
        const float tau = (Sbest - 1.0f) / (float)kbest;

        // normalization sum over candidates (all elements > tau are candidates)
        float s = 0.0f;
        for (int i = lane; i < cnt; i += 32)
            s += fmaxf(s_cand[i] - tau, 0.0f);
#pragma unroll
        for (int o = 16; o > 0; o >>= 1)
            s += __shfl_xor_sync(0xFFFFFFFFu, s, o);
        const float inv = 1.0f / s;

        // ---- sparse deferred writes (no barrier: each warp has tau/inv) ----
        if (dmask) {
#pragma unroll
            for (int j = 0; j < PER_THREAD; j++) {
                if ((dmask >> j) & 1u) {
                    int idx = t + j * THREADS;
                    float4 q = v[j];
                    float4 r;
                    r.x = fmaxf(q.x - tau, 0.0f) * inv;
                    r.y = fmaxf(q.y - tau, 0.0f) * inv;
                    r.z = fmaxf(q.z - tau, 0.0f) * inv;
                    r.w = fmaxf(q.w - tau, 0.0f) * inv;
                    __stcs(&orow[idx], r);
                }
            }
        }
        // wrap: B0 of next iteration protects s_cand/s_cnt reuse
    }
}

extern "C" void kernel_launch(void* const* d_in, const int* in_sizes, int n_in,
                              void* d_out, int out_size)
{
    const float* X = (const float*)d_in[0];
    float* Out     = (float*)d_out;
    const int rows = in_sizes[0] / D_LEN;

    reset_ctr_kernel<<<1, 1>>>();
    sparsemax_kernel<<<152, THREADS>>>(X, Out, rows);
}

// round 4
// speedup vs baseline: 1.3853x; 1.3853x over previous
#include <cuda_runtime.h>
#include <math_constants.h>

// SparsemaxBisect: 4096 rows x 32000 fp32, alpha=2.
// Closed-form sparsemax threshold over the ~20-40 candidates > rowmax-1
// (the reference's 50 bisections converge to exactly this tau).
// Early zero-writes: tau >= warp_max-1, so any float4 whose max is below
// warp_max-1 is exactly 0 in the output and is stored immediately after the
// loads (before any barrier), overlapping 99.9% of store traffic with the
// reduction/collection/solve bubble. Post-solve writes are sparse.

#define D_LEN       32000
#define V4_PER_ROW  8000
#define THREADS     1024
#define NWARP       32
#define PER_THREAD  8
#define CAND_CAP    1024
#define SORT_CAP    256
#define NEG_INF     (-CUDART_INF_F)

__global__ __launch_bounds__(THREADS, 1)
void sparsemax_kernel(const float* __restrict__ X,
                      float* __restrict__ Out)
{
    const int row  = blockIdx.x;
    const int t    = threadIdx.x;
    const int lane = t & 31;
    const int w    = t >> 5;

    const float4* __restrict__ xr =
        reinterpret_cast<const float4*>(X + (size_t)row * D_LEN);
    float4* __restrict__ orow =
        reinterpret_cast<float4*>(Out + (size_t)row * D_LEN);

    __shared__ float s_warpred[NWARP];
    __shared__ float s_tau;
    __shared__ float s_inv;
    __shared__ int   s_cnt;
    __shared__ float s_cand[CAND_CAP];
    __shared__ float s_sorted[SORT_CAP];

    if (t == 0) s_cnt = 0;

    // ---- Phase 1: load row into registers (front-batched LDG.128) ----
    float4 v[PER_THREAD];
#pragma unroll
    for (int j = 0; j < PER_THREAD; j++) {
        int idx = t + j * THREADS;
        v[j] = (idx < V4_PER_ROW) ? __ldcs(&xr[idx])
             : make_float4(NEG_INF, NEG_INF, NEG_INF, NEG_INF);
    }

    // ---- warp max ----
    float wm = NEG_INF;
#pragma unroll
    for (int j = 0; j < PER_THREAD; j++)
        wm = fmaxf(wm, fmaxf(fmaxf(v[j].x, v[j].y), fmaxf(v[j].z, v[j].w)));
#pragma unroll
    for (int o = 16; o > 0; o >>= 1)
        wm = fmaxf(wm, __shfl_xor_sync(0xFFFFFFFFu, wm, o));
    if (lane == 0) s_warpred[w] = wm;
    const float wthr = wm - 1.0f;

    // ---- EARLY zero-writes: float4 max <= warp_max-1 <= tau  =>  exact zeros.
    // Issued before any block barrier; store drain overlaps the bubble. ----
    unsigned dmask = 0u;
    const float4 z4 = make_float4(0.f, 0.f, 0.f, 0.f);
#pragma unroll
    for (int j = 0; j < PER_THREAD; j++) {
        int idx = t + j * THREADS;
        if (idx < V4_PER_ROW) {
            float m4 = fmaxf(fmaxf(v[j].x, v[j].y), fmaxf(v[j].z, v[j].w));
            if (m4 > wthr) dmask |= (1u << j);      // deferred: needs tau
            else           __stcs(&orow[idx], z4);  // final value, write now
        }
    }
    __syncthreads();                                // B1: s_warpred ready

    // ---- global max (each warp redundantly reduces the 32 warp maxima) ----
    float gm = s_warpred[lane];
#pragma unroll
    for (int o = 16; o > 0; o >>= 1)
        gm = fmaxf(gm, __shfl_xor_sync(0xFFFFFFFFu, gm, o));
    const float gthr = gm - 1.0f;

    // ---- candidate collection (round-2 style: cheap guard, ballots on hits) ----
#pragma unroll
    for (int j = 0; j < PER_THREAD; j++) {
        float4 q = v[j];
        float qm = fmaxf(fmaxf(q.x, q.y), fmaxf(q.z, q.w));
        if (__any_sync(0xFFFFFFFFu, qm > gthr)) {
            float c[4] = {q.x, q.y, q.z, q.w};
#pragma unroll
            for (int e = 0; e < 4; e++) {
                bool pred = c[e] > gthr;
                unsigned m = __ballot_sync(0xFFFFFFFFu, pred);
                if (m) {
                    int leader = __ffs(m) - 1;
                    int base = 0;
                    if (lane == leader) base = atomicAdd(&s_cnt, __popc(m));
                    base = __shfl_sync(0xFFFFFFFFu, base, leader);
                    if (pred) {
                        int p = base + __popc(m & ((1u << lane) - 1u));
                        if (p < CAND_CAP) s_cand[p] = c[e];
                    }
                }
            }
        }
    }
    __syncthreads();                                // B2: s_cand ready

    // ---- warp 0 solves tau in closed form ----
    if (t < 32) {
        int cnt = s_cnt;
        cnt = (cnt < SORT_CAP) ? cnt : SORT_CAP;

        // rank-sort descending (O(cnt^2/32), cnt ~ 20-40)
        for (int i = lane; i < cnt; i += 32) {
            float ci = s_cand[i];
            int r = 0;
            for (int jj = 0; jj < cnt; jj++) {
                float cj = s_cand[jj];
                r += (cj > ci) || (cj == ci && jj < i);
            }
            s_sorted[r] = ci;
        }
        __syncwarp();

        // support rule: k* = max{ j : c_(j)*j > S_j - 1 },  tau = (S_k* - 1)/k*
        float Srun = 0.0f;
        int   kbest = 1;
        float Sbest = 0.0f;
        for (int base = 0; base < cnt; base += 32) {
            int idx = base + lane;
            float c = (idx < cnt) ? s_sorted[idx] : 0.0f;
            float x = c;
#pragma unroll
            for (int o = 1; o < 32; o <<= 1) {
                float y = __shfl_up_sync(0xFFFFFFFFu, x, o);
                if (lane >= o) x += y;
            }
            float Sj = Srun + x;
            bool cond = (idx < cnt) && (c * (float)(idx + 1) > Sj - 1.0f);
            unsigned b = __ballot_sync(0xFFFFFFFFu, cond);
            if (b) {
                int hi = 31 - __clz(b);
                Sbest = __shfl_sync(0xFFFFFFFFu, Sj, hi);
                kbest = base + hi + 1;
            }
            Srun += __shfl_sync(0xFFFFFFFFu, x, 31);
        }
        float tau = (Sbest - 1.0f) / (float)kbest;

        // normalization sum (non-candidates contribute exactly 0)
        float s = 0.0f;
        for (int i = lane; i < cnt; i += 32)
            s += fmaxf(s_cand[i] - tau, 0.0f);
#pragma unroll
        for (int o = 16; o > 0; o >>= 1)
            s += __shfl_xor_sync(0xFFFFFFFFu, s, o);

        if (lane == 0) {
            s_tau = tau;
            s_inv = 1.0f / s;
        }
    }
    __syncthreads();                                // B3: tau/inv ready

    const float tau = s_tau;
    const float inv = s_inv;

    // ---- sparse deferred writes (only float4s that could be nonzero) ----
    if (dmask) {
#pragma unroll
        for (int j = 0; j < PER_THREAD; j++) {
            if ((dmask >> j) & 1u) {
                int idx = t + j * THREADS;
                float4 q = v[j];
                float4 r;
                r.x = fmaxf(q.x - tau, 0.0f) * inv;
                r.y = fmaxf(q.y - tau, 0.0f) * inv;
                r.z = fmaxf(q.z - tau, 0.0f) * inv;
                r.w = fmaxf(q.w - tau, 0.0f) * inv;
                __stcs(&orow[idx], r);
            }
        }
    }
}

extern "C" void kernel_launch(void* const* d_in, const int* in_sizes, int n_in,
                              void* d_out, int out_size)
{
    const float* X = (const float*)d_in[0];
    float* Out     = (float*)d_out;
    const int rows = in_sizes[0] / D_LEN;

    sparsemax_kernel<<<rows, THREADS>>>(X, Out);
}